// round 1
// baseline (speedup 1.0000x reference)
#include <cuda_runtime.h>
#include <cuda_bf16.h>
#include <math.h>
#include <stdint.h>

// ---------------- problem constants ----------------
#define NN       8192
#define D_IN     120
#define NODE_D   128
#define HID      64
#define NPW      17536     // num path weights
#define NB       336       // num bias
#define OUTD     60        // out is [N, 60, 60]

// scratch (device globals: allocation-free rule)
__device__ float g_H[NN * HID];
__device__ float g_G[NN * HID];
__device__ float g_bias[NN * NB];
__device__ float g_weight[(size_t)NN * NPW];
__device__ float g_w3j[363];

// ---------------- Wigner 3j init (device, fp64, mirrors reference) ----------------
__device__ double dfac(int n) { double r = 1.0; for (int i = 2; i <= n; i++) r *= (double)i; return r; }
__device__ __forceinline__ int imax3(int a, int b, int c) { int m = a > b ? a : b; return m > c ? m : c; }
__device__ __forceinline__ int imin3(int a, int b, int c) { int m = a < b ? a : b; return m < c ? m : c; }

__device__ void w3j_complex(int j1, int j2, int j3, double* W) {
    int d1 = 2 * j1 + 1, d2 = 2 * j2 + 1, d3 = 2 * j3 + 1;
    for (int a = 0; a < d1 * d2 * d3; a++) W[a] = 0.0;
    double tri = dfac(j1 + j2 - j3) * dfac(j1 - j2 + j3) * dfac(-j1 + j2 + j3) / dfac(j1 + j2 + j3 + 1);
    for (int m1 = -j1; m1 <= j1; m1++) {
        for (int m2 = -j2; m2 <= j2; m2++) {
            int m3 = -m1 - m2;
            if (m3 < -j3 || m3 > j3) continue;
            double pref = sqrt(tri * dfac(j1 + m1) * dfac(j1 - m1) * dfac(j2 + m2)
                               * dfac(j2 - m2) * dfac(j3 + m3) * dfac(j3 - m3));
            int t0 = imax3(0, j2 - j3 - m1, j1 - j3 + m2);
            int t1 = imin3(j1 + j2 - j3, j1 - m1, j2 + m2);
            double s = 0.0;
            for (int t = t0; t <= t1; t++) {
                double den = dfac(t) * dfac(j1 + j2 - j3 - t) * dfac(j1 - m1 - t)
                           * dfac(j2 + m2 - t) * dfac(j3 - j2 + m1 + t) * dfac(j3 - j1 - m2 + t);
                s += ((t & 1) ? -1.0 : 1.0) / den;
            }
            double sign = (((j1 - j2 - m3) & 1) ? -1.0 : 1.0);
            W[((m1 + j1) * d2 + (m2 + j2)) * d3 + (m3 + j3)] = sign * pref * s;
        }
    }
}

__device__ void u_real(int l, double* Ur, double* Ui) {
    int d = 2 * l + 1;
    for (int a = 0; a < d * d; a++) { Ur[a] = 0.0; Ui[a] = 0.0; }
    Ur[l * d + l] = 1.0;
    double s = 1.0 / sqrt(2.0);
    for (int m = 1; m <= l; m++) {
        double pm = ((m & 1) ? -1.0 : 1.0);
        Ur[(l + m) * d + (l + m)] = pm * s;
        Ur[(l + m) * d + (l - m)] = s;
        Ui[(l - m) * d + (l - m)] = s;
        Ui[(l - m) * d + (l + m)] = -pm * s;
    }
}

__global__ void w3j_init_kernel() {
    int p = threadIdx.x;
    if (p >= 11) return;
    const int L1[11]  = {0,1,2, 0,1,1,2, 0,1,2,2};
    const int L2[11]  = {0,1,2, 1,0,2,1, 2,1,0,2};
    const int LI[11]  = {0,0,0, 1,1,1,1, 2,2,2,2};
    const int OFF[11] = {0,1,10,35,44,53,98,143,168,213,238};
    int j1 = L1[p], j2 = L2[p], j3 = LI[p];
    int d1 = 2 * j1 + 1, d2 = 2 * j2 + 1, d3 = 2 * j3 + 1;

    double W[125];
    w3j_complex(j1, j2, j3, W);
    double U1r[25], U1i[25], U2r[25], U2i[25], U3r[25], U3i[25];
    u_real(j1, U1r, U1i);
    u_real(j2, U2r, U2i);
    u_real(j3, U3r, U3i);

    for (int i = 0; i < d1; i++)
        for (int j = 0; j < d2; j++)
            for (int k = 0; k < d3; k++) {
                double re = 0.0;
                for (int m = 0; m < d1; m++)
                    for (int nn = 0; nn < d2; nn++) {
                        double ar = U1r[i * d1 + m] * U2r[j * d2 + nn] - U1i[i * d1 + m] * U2i[j * d2 + nn];
                        double ai = U1r[i * d1 + m] * U2i[j * d2 + nn] + U1i[i * d1 + m] * U2r[j * d2 + nn];
                        for (int pp = 0; pp < d3; pp++) {
                            double w = W[(m * d2 + nn) * d3 + pp];
                            if (w == 0.0) continue;
                            double br = ar * U3r[k * d3 + pp] - ai * U3i[k * d3 + pp];
                            re += br * w;
                        }
                    }
                g_w3j[OFF[p] + (i * d2 + j) * d3 + k] = (float)re;
            }
}

// ---------------- hidden layers: H = silu(embed@w1w+b1w), G = silu(embed@w1b+b1b) ----------------
__global__ __launch_bounds__(128) void hidden_kernel(
    const float* __restrict__ embed,
    const float* __restrict__ w1w, const float* __restrict__ b1w,
    const float* __restrict__ w1b, const float* __restrict__ b1b) {
    __shared__ float se[NODE_D];
    int n = blockIdx.x, tid = threadIdx.x;
    se[tid] = embed[n * NODE_D + tid];
    __syncthreads();
    int t = tid & 63;
    const float* wmat = (tid < 64) ? w1w : w1b;
    const float* bvec = (tid < 64) ? b1w : b1b;
    float acc = bvec[t];
    #pragma unroll 8
    for (int h = 0; h < NODE_D; h++) acc += se[h] * wmat[h * HID + t];
    float s = acc / (1.0f + expf(-acc));
    if (tid < 64) g_H[n * HID + t] = s;
    else          g_G[n * HID + t] = s;
}

// ---------------- bias: bias = G @ w2b + b2b  [N, 336] ----------------
__global__ __launch_bounds__(352) void bias_kernel(
    const float* __restrict__ w2b, const float* __restrict__ b2b) {
    __shared__ float sg[HID];
    int n = blockIdx.x, tid = threadIdx.x;
    if (tid < HID) sg[tid] = g_G[n * HID + tid];
    __syncthreads();
    if (tid < NB) {
        float acc = b2b[tid];
        #pragma unroll 8
        for (int h = 0; h < HID; h++) acc += sg[h] * w2b[h * NB + tid];
        g_bias[n * NB + tid] = acc;
    }
}

// ---------------- weight GEMM: g_weight = H @ w2w + b2w  [8192 x 17536], K=64 ----------------
// tile: 64 nodes x 128 cols, K=64 fully resident in smem.
__global__ __launch_bounds__(256) void gemm_kernel(
    const float* __restrict__ w2w, const float* __restrict__ b2w) {
    __shared__ float Hs[64 * 64];    // [m][k]
    __shared__ float Ws[64 * 128];   // [k][n]
    int m0 = blockIdx.y * 64;
    int n0 = blockIdx.x * 128;
    int tid = threadIdx.x;

    for (int idx = tid; idx < 64 * 64; idx += 256) {
        int m = idx >> 6, k = idx & 63;
        Hs[idx] = g_H[(m0 + m) * HID + k];
    }
    for (int idx = tid; idx < 64 * 128; idx += 256) {
        int k = idx >> 7, nn = idx & 127;
        Ws[idx] = w2w[k * NPW + n0 + nn];
    }
    __syncthreads();

    int tm = (tid >> 5) * 8;    // warp-uniform row group
    int tn = (tid & 31) * 4;    // 4 cols per thread
    float acc[8][4];
    #pragma unroll
    for (int r = 0; r < 8; r++)
        #pragma unroll
        for (int c = 0; c < 4; c++) acc[r][c] = 0.0f;

    #pragma unroll 4
    for (int k = 0; k < 64; k++) {
        float4 b = *(const float4*)&Ws[k * 128 + tn];
        #pragma unroll
        for (int r = 0; r < 8; r++) {
            float a = Hs[(tm + r) * 64 + k];
            acc[r][0] += a * b.x;
            acc[r][1] += a * b.y;
            acc[r][2] += a * b.z;
            acc[r][3] += a * b.w;
        }
    }

    float4 bb = *(const float4*)&b2w[n0 + tn];
    #pragma unroll
    for (int r = 0; r < 8; r++) {
        float4 o;
        o.x = acc[r][0] + bb.x;
        o.y = acc[r][1] + bb.y;
        o.z = acc[r][2] + bb.z;
        o.w = acc[r][3] + bb.w;
        *(float4*)&g_weight[(size_t)(m0 + tm + r) * NPW + n0 + tn] = o;
    }
}

// ---------------- per-node expansion ----------------
template<int MUL_IN, int MUL1, int MUL2, int D1, int D2, int DI,
         int W_OFF, int B_OFF, int W3J_OFF, int ROW_OFF, int COL_OFF, int X_OFF>
__device__ __forceinline__ void do_path(const float* __restrict__ wrow,
                                        const float* xsh, const float* bsh,
                                        const float* w3s, float* osh, int tid) {
    constexpr int UV = MUL1 * MUL2;
    if (tid < UV) {
        int u = tid / MUL2, v = tid % MUL2;
        float res[DI];
        #pragma unroll
        for (int k = 0; k < DI; k++) res[k] = 0.0f;
        const float* wp = wrow + W_OFF + tid;
        #pragma unroll
        for (int w = 0; w < MUL_IN; w++) {
            float wt = wp[w * UV];
            #pragma unroll
            for (int k = 0; k < DI; k++) res[k] += wt * xsh[X_OFF + w * DI + k];
        }
        if (B_OFF >= 0) res[0] += bsh[B_OFF + tid];
        constexpr float inv = 1.0f / (float)MUL_IN;
        #pragma unroll
        for (int a = 0; a < D1; a++) {
            #pragma unroll
            for (int b = 0; b < D2; b++) {
                float acc = 0.0f;
                #pragma unroll
                for (int k = 0; k < DI; k++)
                    acc += w3s[W3J_OFF + (a * D2 + b) * DI + k] * res[k];
                osh[(ROW_OFF + u * D1 + a) * OUTD + COL_OFF + v * D2 + b] += acc * inv;
            }
        }
    }
    __syncthreads();
}

__global__ __launch_bounds__(256) void expand_kernel(
    const float* __restrict__ x_in, float* __restrict__ out) {
    __shared__ float xsh[D_IN];
    __shared__ float bsh[NB];
    __shared__ float w3s[363];
    __shared__ float osh[OUTD * OUTD];
    int n = blockIdx.x, tid = threadIdx.x;
    const float* wrow = g_weight + (size_t)n * NPW;

    if (tid < D_IN) xsh[tid] = x_in[n * D_IN + tid];
    for (int i = tid; i < NB; i += 256) bsh[i] = g_bias[n * NB + i];
    for (int i = tid; i < 363; i += 256) w3s[i] = g_w3j[i];
    for (int i = tid; i < OUTD * OUTD; i += 256) osh[i] = 0.0f;
    __syncthreads();

    //        MUL_IN MUL1 MUL2 D1 D2 DI  W_OFF  B_OFF W3J ROW COL X_OFF
    do_path<32, 16, 16, 1, 1, 1,     0,   0,   0,   0,  0,  0>(wrow, xsh, bsh, w3s, osh, tid);
    do_path<32,  8,  8, 3, 3, 1,  8192, 256,   1,  16, 16,  0>(wrow, xsh, bsh, w3s, osh, tid);
    do_path<32,  4,  4, 5, 5, 1, 10240, 320,  10,  40, 40,  0>(wrow, xsh, bsh, w3s, osh, tid);
    do_path<16, 16,  8, 1, 3, 3, 10752,  -1,  35,   0, 16, 32>(wrow, xsh, bsh, w3s, osh, tid);
    do_path<16,  8, 16, 3, 1, 3, 12800,  -1,  44,  16,  0, 32>(wrow, xsh, bsh, w3s, osh, tid);
    do_path<16,  8,  4, 3, 5, 3, 14848,  -1,  53,  16, 40, 32>(wrow, xsh, bsh, w3s, osh, tid);
    do_path<16,  4,  8, 5, 3, 3, 15360,  -1,  98,  40, 16, 32>(wrow, xsh, bsh, w3s, osh, tid);
    do_path< 8, 16,  4, 1, 5, 5, 15872,  -1, 143,   0, 40, 80>(wrow, xsh, bsh, w3s, osh, tid);
    do_path< 8,  8,  8, 3, 3, 5, 16384,  -1, 168,  16, 16, 80>(wrow, xsh, bsh, w3s, osh, tid);
    do_path< 8,  4, 16, 5, 1, 5, 16896,  -1, 213,  40,  0, 80>(wrow, xsh, bsh, w3s, osh, tid);
    do_path< 8,  4,  4, 5, 5, 5, 17408,  -1, 238,  40, 40, 80>(wrow, xsh, bsh, w3s, osh, tid);

    for (int i = tid; i < OUTD * OUTD; i += 256)
        out[(size_t)n * (OUTD * OUTD) + i] = osh[i];
}

// ---------------- launch ----------------
extern "C" void kernel_launch(void* const* d_in, const int* in_sizes, int n_in,
                              void* d_out, int out_size) {
    const float* x_in  = (const float*)d_in[0];
    const float* embed = (const float*)d_in[1];
    const float* w1w   = (const float*)d_in[2];
    const float* b1w   = (const float*)d_in[3];
    const float* w2w   = (const float*)d_in[4];
    const float* b2w   = (const float*)d_in[5];
    const float* w1b   = (const float*)d_in[6];
    const float* b1b   = (const float*)d_in[7];
    const float* w2b   = (const float*)d_in[8];
    const float* b2b   = (const float*)d_in[9];
    float* out = (float*)d_out;

    w3j_init_kernel<<<1, 32>>>();
    hidden_kernel<<<NN, 128>>>(embed, w1w, b1w, w1b, b1b);
    bias_kernel<<<NN, 352>>>(w2b, b2b);
    gemm_kernel<<<dim3(NPW / 128, NN / 64), 256>>>(w2w, b2w);
    expand_kernel<<<NN, 256>>>(x_in, out);
}